// round 2
// baseline (speedup 1.0000x reference)
#include <cuda_runtime.h>
#include <cuda_bf16.h>
#include <math.h>

#define PAD 8192
#define B 32
#define K 32
#define L 128
#define H1 512
#define H2 64

// scratch (device globals; fully rewritten every launch)
__device__ float g_qh[B * H2];          // query_hidden
__device__ float g_ts[B * K];           // text_sim

__device__ __forceinline__ float prelu(float x, float a) {
    return x >= 0.f ? x : a * x;
}

// ---------------------------------------------------------------------------
// Kernel 1: query embedding bag + 2-layer MLP  (32 blocks x 256 threads)
// ---------------------------------------------------------------------------
__global__ void query_kernel(const int* __restrict__ qbf,
                             const float* __restrict__ cw,
                             const float* __restrict__ W1,
                             const float* __restrict__ b1,
                             const float* __restrict__ W2,
                             const float* __restrict__ b2,
                             const float* __restrict__ a0p,
                             const float* __restrict__ a1p,
                             const float* __restrict__ a2p) {
    __shared__ int   idx[L];
    __shared__ float x[H1];
    __shared__ float partial[256];
    __shared__ float h1[H2];

    const int b = blockIdx.x;
    const int tid = threadIdx.x;
    const float a0 = *a0p, a1 = *a1p, a2 = *a2p;

    if (tid < L) idx[tid] = qbf[b * L + tid];
    __syncthreads();

    // embedding bag mean over L indices, thread handles dims tid and tid+256
    float acc0 = 0.f, acc1 = 0.f;
    int cnt = 0;
#pragma unroll 4
    for (int l = 0; l < L; l++) {
        int v = idx[l];
        if (v != PAD) {
            const float* row = cw + (size_t)v * H1;
            acc0 += row[tid];
            acc1 += row[tid + 256];
            cnt++;
        }
    }
    float inv = cnt > 0 ? 1.f / (float)cnt : 0.f;
    x[tid]       = prelu(acc0 * inv, a0);
    x[tid + 256] = prelu(acc1 * inv, a0);
    __syncthreads();

    // MLP1: 512 -> 64, 4-way split over d per output j
    {
        int j = tid >> 2, part = tid & 3;
        float acc = 0.f;
        int d0 = part * 128;
#pragma unroll 8
        for (int d = 0; d < 128; d++) {
            acc = fmaf(x[d0 + d], W1[(d0 + d) * H2 + j], acc);
        }
        partial[tid] = acc;
    }
    __syncthreads();
    if (tid < H2) {
        float acc = b1[tid] + partial[tid * 4] + partial[tid * 4 + 1] +
                    partial[tid * 4 + 2] + partial[tid * 4 + 3];
        h1[tid] = prelu(acc, a1);
    }
    __syncthreads();
    if (tid < H2) {
        float acc = b2[tid];
#pragma unroll 8
        for (int d = 0; d < H2; d++) acc = fmaf(h1[d], W2[d * H2 + tid], acc);
        g_qh[b * H2 + tid] = prelu(acc, a2);
    }
}

// ---------------------------------------------------------------------------
// Kernel 2: poi embedding + MLP for 4 (b,k) pairs per block, fused with
// sparse intersection / text_sim.  grid = 1024/4 = 256 blocks x 256 threads.
// ---------------------------------------------------------------------------
#define BAGS 4
#define XS 520   // padded stride for x  (520 % 32 == 8 -> conflict-free g lanes)
#define HS 68    // padded stride for h1/ph (68 % 32 == 4)

__global__ void poi_kernel(const int* __restrict__ qbf,
                           const int* __restrict__ pbf,
                           const float* __restrict__ cw,
                           const float* __restrict__ W1,
                           const float* __restrict__ b1,
                           const float* __restrict__ W2,
                           const float* __restrict__ b2,
                           const float* __restrict__ qew,
                           const float* __restrict__ pew,
                           const float* __restrict__ a0p,
                           const float* __restrict__ a1p,
                           const float* __restrict__ a2p,
                           const float* __restrict__ indap) {
    __shared__ int   pidx[BAGS * L];
    __shared__ int   qidx[BAGS * L];
    __shared__ float x[BAGS * XS];
    __shared__ float h1s[BAGS * HS];
    __shared__ float phs[BAGS * HS];
    __shared__ float qhs[BAGS * H2];
    __shared__ float red[BAGS * L];

    const int tid = threadIdx.x;
    const int pair0 = blockIdx.x * BAGS;
    const float a0 = *a0p, a1 = *a1p, a2 = *a2p, ind_a = *indap;

    // load p indices (4*128) and q indices (per-pair b)
    for (int t = tid; t < BAGS * L; t += 256) {
        int g = t >> 7, i = t & (L - 1);
        pidx[t] = pbf[(size_t)(pair0 + g) * L + i];
        qidx[t] = qbf[(size_t)((pair0 + g) >> 5) * L + i];
    }
    // load query_hidden for each pair's b
    for (int t = tid; t < BAGS * H2; t += 256) {
        int g = t >> 6, h = t & (H2 - 1);
        qhs[t] = g_qh[(size_t)((pair0 + g) >> 5) * H2 + h];
    }
    __syncthreads();

    // ---- embedding bags (sequential over the 4 bags) ----
    for (int g = 0; g < BAGS; g++) {
        const int* pi = &pidx[g * L];
        float acc0 = 0.f, acc1 = 0.f;
        int cnt = 0;
#pragma unroll 4
        for (int l = 0; l < L; l++) {
            int v = pi[l];
            if (v != PAD) {
                const float* row = cw + (size_t)v * H1;
                acc0 += row[tid];
                acc1 += row[tid + 256];
                cnt++;
            }
        }
        float inv = cnt > 0 ? 1.f / (float)cnt : 0.f;
        x[g * XS + tid]       = prelu(acc0 * inv, a0);
        x[g * XS + tid + 256] = prelu(acc1 * inv, a0);
    }
    __syncthreads();

    // ---- MLP1: each thread = (output j, bag g); W1 elem read once per block/4 bags
    {
        int j = tid >> 2, g = tid & 3;
        const float* xg = &x[g * XS];
        float acc = b1[j];
#pragma unroll 8
        for (int d = 0; d < H1; d++) acc = fmaf(xg[d], W1[d * H2 + j], acc);
        h1s[g * HS + j] = prelu(acc, a1);
    }
    __syncthreads();
    // ---- MLP2
    {
        int j = tid >> 2, g = tid & 3;
        const float* hg = &h1s[g * HS];
        float acc = b2[j];
#pragma unroll 8
        for (int d = 0; d < H2; d++) acc = fmaf(hg[d], W2[d * H2 + j], acc);
        phs[g * HS + j] = prelu(acc, a2);
    }
    __syncthreads();

    // ---- sparse intersection + text_sim terms ----
    for (int r = 0; r < 2; r++) {
        int t = tid + r * 256;           // 512 tasks: (g, i)
        int g = t >> 7, i = t & (L - 1);
        int v = qidx[g * L + i];
        float val = 0.f;
        if (v != PAD) {
            const int* pp = &pidx[g * L];
            bool found = false;
            for (int jj = 0; jj < L; jj++) {
                if (pp[jj] == v) { found = true; break; }
            }
            if (found) {
                const float* qr = qew + (size_t)v * H2;
                const float* pr = pew + (size_t)v * H2;
                const float* qh = &qhs[g * H2];
                const float* ph = &phs[g * HS];
                float qd = 0.f, pd = 0.f;
#pragma unroll 8
                for (int h = 0; h < H2; h++) {
                    qd = fmaf(qh[h], qr[h], qd);
                    pd = fmaf(ph[h], pr[h], pd);
                }
                float qs = prelu(qd, ind_a) + 1.f;
                float ps = prelu(pd, ind_a) + 1.f;
                val = qs * ps;
            }
        }
        red[t] = (r == 0) ? val : red[t] + 0.f, red[t] = 0.f;  // placeholder (overwritten below)
        red[t] = val;
    }
    __syncthreads();

    // deterministic tree reduction within each bag's 128 entries
    for (int s = 64; s > 0; s >>= 1) {
        if (tid < BAGS * s) {
            int g = tid / s, i = tid - g * s;
            red[g * L + i] += red[g * L + i + s];
        }
        __syncthreads();
    }
    if (tid < BAGS) g_ts[pair0 + tid] = red[tid * L];
}

// ---------------------------------------------------------------------------
// Kernel 3: per-b max over k, distance term, final score. 32 blocks x 32 thr.
// ---------------------------------------------------------------------------
__global__ void final_kernel(const float* __restrict__ qloc,
                             const float* __restrict__ ploc,
                             const float* __restrict__ ap,
                             const float* __restrict__ bp,
                             const float* __restrict__ cp,
                             const float* __restrict__ dp,
                             float* __restrict__ out) {
    int b = blockIdx.x;
    int k = threadIdx.x;
    float ts = g_ts[b * K + k];
    float m = ts;
#pragma unroll
    for (int off = 16; off > 0; off >>= 1)
        m = fmaxf(m, __shfl_xor_sync(0xffffffffu, m, off));
    float tsn = (2.f * ts - m) / (m + 1e-6f);
    float dx = qloc[b * 2]     - ploc[(b * K + k) * 2];
    float dy = qloc[b * 2 + 1] - ploc[(b * K + k) * 2 + 1];
    float dist = sqrtf(dx * dx + dy * dy);
    float dist_sim = -logf(dist + 1.f);
    float A = *ap, Bc = *bp, C = *cp, D = *dp;
    float sig = 1.f / (1.f + expf(-(A * tsn + Bc)));
    out[b * K + k] = (C - sig) * (dist_sim - D);
}

// ---------------------------------------------------------------------------
extern "C" void kernel_launch(void* const* d_in, const int* in_sizes, int n_in,
                              void* d_out, int out_size) {
    const int*   qbf  = (const int*)d_in[0];
    const int*   pbf  = (const int*)d_in[1];
    const float* qloc = (const float*)d_in[2];
    const float* ploc = (const float*)d_in[3];
    const float* cw   = (const float*)d_in[4];
    const float* qW1  = (const float*)d_in[5];
    const float* qb1  = (const float*)d_in[6];
    const float* qW2  = (const float*)d_in[7];
    const float* qb2  = (const float*)d_in[8];
    const float* pW1  = (const float*)d_in[9];
    const float* pb1  = (const float*)d_in[10];
    const float* pW2  = (const float*)d_in[11];
    const float* pb2  = (const float*)d_in[12];
    const float* qew  = (const float*)d_in[13];
    const float* pew  = (const float*)d_in[14];
    const float* qa0  = (const float*)d_in[15];
    const float* qa1  = (const float*)d_in[16];
    const float* qa2  = (const float*)d_in[17];
    const float* pa0  = (const float*)d_in[18];
    const float* pa1  = (const float*)d_in[19];
    const float* pa2  = (const float*)d_in[20];
    const float* inda = (const float*)d_in[21];
    const float* a    = (const float*)d_in[22];
    const float* b    = (const float*)d_in[23];
    const float* c    = (const float*)d_in[24];
    const float* d    = (const float*)d_in[25];
    float* out = (float*)d_out;

    query_kernel<<<B, 256>>>(qbf, cw, qW1, qb1, qW2, qb2, qa0, qa1, qa2);
    poi_kernel<<<(B * K) / BAGS, 256>>>(qbf, pbf, cw, pW1, pb1, pW2, pb2,
                                        qew, pew, pa0, pa1, pa2, inda);
    final_kernel<<<B, K>>>(qloc, ploc, a, b, c, d, out);
}

// round 4
// speedup vs baseline: 1.5166x; 1.5166x over previous
#include <cuda_runtime.h>
#include <cuda_bf16.h>
#include <math.h>

#define PAD 8192
#define B 32
#define K 32
#define L 128
#define H1 512
#define H2 64
#define BAGS 4
#define NT 384
#define XS 516   // float stride per bag for x; 516*4 = 2064 bytes, 16B multiple
#define HS 68

// scratch (device global; fully rewritten every launch)
__device__ float g_ts[B * K];

__device__ __forceinline__ float prelu(float x, float a) {
    return x >= 0.f ? x : a * x;
}

// ---------------------------------------------------------------------------
// Fused kernel: query bag+MLP (recomputed per block), 4 poi bags+MLP,
// bitmap intersection, text_sim reduction.  grid = 256 blocks x 384 threads.
// All 4 (b,k) pairs of a block share the same b.
// ---------------------------------------------------------------------------
__global__ __launch_bounds__(NT, 2)
void fused_kernel(const int* __restrict__ qbf,
                  const int* __restrict__ pbf,
                  const float* __restrict__ cw,
                  const float* __restrict__ qW1, const float* __restrict__ qb1,
                  const float* __restrict__ qW2, const float* __restrict__ qb2,
                  const float* __restrict__ pW1, const float* __restrict__ pb1,
                  const float* __restrict__ pW2, const float* __restrict__ pb2,
                  const float* __restrict__ qew, const float* __restrict__ pew,
                  const float* __restrict__ qa0p, const float* __restrict__ qa1p,
                  const float* __restrict__ qa2p, const float* __restrict__ pa0p,
                  const float* __restrict__ pa1p, const float* __restrict__ pa2p,
                  const float* __restrict__ indap) {
    __shared__ int      qidx[L];
    __shared__ int      pidx[BAGS * L];
    __shared__ unsigned bitmap[BAGS * 256];   // 8192 bits per bag
    __shared__ float    counts_inv[5];
    __shared__ __align__(16) float qx[H1];    // query embedding (post-prelu)
    __shared__ __align__(16) float x[BAGS * XS]; // poi embeddings (post-prelu)
    __shared__ float    qh1[H2];
    __shared__ float    qh[H2];               // query_hidden
    __shared__ float    h1s[BAGS * HS];
    __shared__ float    phs[BAGS * HS];       // poi_hidden
    __shared__ float    qsw[L];               // q-side switch, per query index i
    __shared__ float    red[BAGS * L];

    const int tid = threadIdx.x;
    const int pair0 = blockIdx.x * BAGS;
    const int bb = pair0 >> 5;                // same b for all 4 pairs
    const float qa0 = *qa0p, qa1 = *qa1p, qa2 = *qa2p;
    const float pa0 = *pa0p, pa1 = *pa1p, pa2 = *pa2p;
    const float ind_a = *indap;

    // ---- stage 0: load index lists, zero bitmap ----
    for (int t = tid; t < BAGS * L; t += NT)
        pidx[t] = pbf[(size_t)pair0 * L + t];
    for (int t = tid; t < L; t += NT)
        qidx[t] = qbf[(size_t)bb * L + t];
    for (int t = tid; t < BAGS * 256; t += NT)
        bitmap[t] = 0u;
    __syncthreads();

    // ---- stage 1: counts + bitmap build ----
    if (tid < 5) {
        const int* ip = (tid == 0) ? qidx : &pidx[(tid - 1) * L];
        int c = 0;
#pragma unroll 8
        for (int l = 0; l < L; l++) c += (ip[l] != PAD);
        counts_inv[tid] = (c > 0) ? 1.f / (float)c : 0.f;
    }
    for (int t = tid; t < BAGS * L; t += NT) {
        int v = pidx[t];
        if (v != PAD)
            atomicOr(&bitmap[(t >> 7) * 256 + (v >> 5)], 1u << (v & 31));
    }
    __syncthreads();

    // ---- stage 2: 5 embedding bags in 2 phases (float4 gathers) ----
    {
        const int ft = tid & 127;       // float4 slot within 512-float row
        const int group = tid >> 7;     // 0..2
        const float4* cw4 = (const float4*)cw;
#pragma unroll
        for (int phase = 0; phase < 2; phase++) {
            int task = phase * 3 + group;   // 0=query, 1..4=poi bags
            if (task <= 4) {
                const int* ip = (task == 0) ? qidx : &pidx[(task - 1) * L];
                float alpha = (task == 0) ? qa0 : pa0;
                float4 acc = make_float4(0.f, 0.f, 0.f, 0.f);
#pragma unroll 4
                for (int l = 0; l < L; l++) {
                    int v = ip[l];
                    if (v != PAD) {
                        float4 r = __ldg(cw4 + (size_t)v * 128 + ft);
                        acc.x += r.x; acc.y += r.y; acc.z += r.z; acc.w += r.w;
                    }
                }
                float inv = counts_inv[task];
                float4 o;
                o.x = prelu(acc.x * inv, alpha);
                o.y = prelu(acc.y * inv, alpha);
                o.z = prelu(acc.z * inv, alpha);
                o.w = prelu(acc.w * inv, alpha);
                float* dst = (task == 0) ? qx : &x[(task - 1) * XS];
                *(float4*)(dst + ft * 4) = o;
            }
        }
    }
    __syncthreads();

    // ---- stage 3: MLP layer 1 (coalesced: j = lanes, g fixed per warp) ----
    {
        const int j = tid & 63, g = tid >> 6;   // g: 0-3 poi, 4 query, 5 idle
        if (g < 4) {
            const float* xg = &x[g * XS];
            float acc = pb1[j];
#pragma unroll 8
            for (int d = 0; d < H1; d++) acc = fmaf(xg[d], pW1[d * H2 + j], acc);
            h1s[g * HS + j] = prelu(acc, pa1);
        } else if (g == 4) {
            float acc = qb1[j];
#pragma unroll 8
            for (int d = 0; d < H1; d++) acc = fmaf(qx[d], qW1[d * H2 + j], acc);
            qh1[j] = prelu(acc, qa1);
        }
    }
    __syncthreads();

    // ---- stage 4: MLP layer 2 ----
    {
        const int j = tid & 63, g = tid >> 6;
        if (g < 4) {
            const float* hg = &h1s[g * HS];
            float acc = pb2[j];
#pragma unroll 8
            for (int d = 0; d < H2; d++) acc = fmaf(hg[d], pW2[d * H2 + j], acc);
            phs[g * HS + j] = prelu(acc, pa2);
        } else if (g == 4) {
            float acc = qb2[j];
#pragma unroll 8
            for (int d = 0; d < H2; d++) acc = fmaf(qh1[d], qW2[d * H2 + j], acc);
            qh[j] = prelu(acc, qa2);
        }
    }
    __syncthreads();

    // ---- stage 5: q-side switch, once per query index i (shared across bags) ----
    if (tid < L) {
        int v = qidx[tid];
        float s = 0.f;
        if (v != PAD) {
            const float* qr = qew + (size_t)v * H2;
            float qd = 0.f;
#pragma unroll 8
            for (int h = 0; h < H2; h++) qd = fmaf(qh[h], __ldg(qr + h), qd);
            s = prelu(qd, ind_a) + 1.f;
        }
        qsw[tid] = s;
    }
    __syncthreads();

    // ---- stage 6: intersection probe + p-side dot (sparse: ~8 hits/block) ----
    for (int t = tid; t < BAGS * L; t += NT) {
        int g = t >> 7, i = t & (L - 1);
        int v = qidx[i];
        float val = 0.f;
        if (v != PAD && (bitmap[g * 256 + (v >> 5)] >> (v & 31)) & 1u) {
            const float* pr = pew + (size_t)v * H2;
            const float* ph = &phs[g * HS];
            float pd = 0.f;
#pragma unroll 8
            for (int h = 0; h < H2; h++) pd = fmaf(ph[h], __ldg(pr + h), pd);
            val = qsw[i] * (prelu(pd, ind_a) + 1.f);
        }
        red[t] = val;
    }
    __syncthreads();

    // ---- stage 7: deterministic tree reduction, 128 -> 1 per bag ----
    for (int s = 64; s > 0; s >>= 1) {
        if (tid < BAGS * s) {
            int g = tid / s, i = tid - g * s;
            red[g * L + i] += red[g * L + i + s];
        }
        __syncthreads();
    }
    if (tid < BAGS) g_ts[pair0 + tid] = red[tid * L];
}

// ---------------------------------------------------------------------------
// Final kernel: per-b max over k, distance term, score. 32 blocks x 32 thr.
// ---------------------------------------------------------------------------
__global__ void final_kernel(const float* __restrict__ qloc,
                             const float* __restrict__ ploc,
                             const float* __restrict__ ap,
                             const float* __restrict__ bp,
                             const float* __restrict__ cp,
                             const float* __restrict__ dp,
                             float* __restrict__ out) {
    int b = blockIdx.x;
    int k = threadIdx.x;
    float ts = g_ts[b * K + k];
    float m = ts;
#pragma unroll
    for (int off = 16; off > 0; off >>= 1)
        m = fmaxf(m, __shfl_xor_sync(0xffffffffu, m, off));
    float tsn = (2.f * ts - m) / (m + 1e-6f);
    float dx = qloc[b * 2]     - ploc[(b * K + k) * 2];
    float dy = qloc[b * 2 + 1] - ploc[(b * K + k) * 2 + 1];
    float dist = sqrtf(dx * dx + dy * dy);
    float dist_sim = -logf(dist + 1.f);
    float A = *ap, Bc = *bp, C = *cp, D = *dp;
    float sig = 1.f / (1.f + expf(-(A * tsn + Bc)));
    out[b * K + k] = (C - sig) * (dist_sim - D);
}

// ---------------------------------------------------------------------------
extern "C" void kernel_launch(void* const* d_in, const int* in_sizes, int n_in,
                              void* d_out, int out_size) {
    const int*   qbf  = (const int*)d_in[0];
    const int*   pbf  = (const int*)d_in[1];
    const float* qloc = (const float*)d_in[2];
    const float* ploc = (const float*)d_in[3];
    const float* cw   = (const float*)d_in[4];
    const float* qW1  = (const float*)d_in[5];
    const float* qb1  = (const float*)d_in[6];
    const float* qW2  = (const float*)d_in[7];
    const float* qb2  = (const float*)d_in[8];
    const float* pW1  = (const float*)d_in[9];
    const float* pb1  = (const float*)d_in[10];
    const float* pW2  = (const float*)d_in[11];
    const float* pb2  = (const float*)d_in[12];
    const float* qew  = (const float*)d_in[13];
    const float* pew  = (const float*)d_in[14];
    const float* qa0  = (const float*)d_in[15];
    const float* qa1  = (const float*)d_in[16];
    const float* qa2  = (const float*)d_in[17];
    const float* pa0  = (const float*)d_in[18];
    const float* pa1  = (const float*)d_in[19];
    const float* pa2  = (const float*)d_in[20];
    const float* inda = (const float*)d_in[21];
    const float* a    = (const float*)d_in[22];
    const float* b    = (const float*)d_in[23];
    const float* c    = (const float*)d_in[24];
    const float* d    = (const float*)d_in[25];
    float* out = (float*)d_out;

    fused_kernel<<<(B * K) / BAGS, NT>>>(qbf, pbf, cw,
                                         qW1, qb1, qW2, qb2,
                                         pW1, pb1, pW2, pb2,
                                         qew, pew,
                                         qa0, qa1, qa2, pa0, pa1, pa2, inda);
    final_kernel<<<B, K>>>(qloc, ploc, a, b, c, d, out);
}

// round 5
// speedup vs baseline: 1.8536x; 1.2222x over previous
#include <cuda_runtime.h>
#include <cuda_bf16.h>
#include <math.h>

#define PAD 8192
#define B 32
#define K 32
#define L 128
#define H1 512
#define H2 64
#define BAGS 4
#define NT 512
#define XS 516          // float stride per poi bag (2064 B, 16B multiple)
#define HS 68
#define NQBLK 32        // query blocks
#define NPBLK 256       // poi blocks
#define NBLK (NQBLK + NPBLK)

// device-global scratch (zero-init at load; kernel restores zeros for flags/counter)
__device__ float g_qh[B * H2];
__device__ float g_ts[B * K];
__device__ int   g_qflag[B];
__device__ int   g_counter;

__device__ __forceinline__ float prelu(float x, float a) {
    return x >= 0.f ? x : a * x;
}

__global__ __launch_bounds__(NT, 2)
void urban_kernel(const int* __restrict__ qbf,
                  const int* __restrict__ pbf,
                  const float* __restrict__ qloc,
                  const float* __restrict__ ploc,
                  const float* __restrict__ cw,
                  const float* __restrict__ qW1, const float* __restrict__ qb1,
                  const float* __restrict__ qW2, const float* __restrict__ qb2,
                  const float* __restrict__ pW1, const float* __restrict__ pb1,
                  const float* __restrict__ pW2, const float* __restrict__ pb2,
                  const float* __restrict__ qew, const float* __restrict__ pew,
                  const float* __restrict__ qa0p, const float* __restrict__ qa1p,
                  const float* __restrict__ qa2p, const float* __restrict__ pa0p,
                  const float* __restrict__ pa1p, const float* __restrict__ pa2p,
                  const float* __restrict__ indap,
                  const float* __restrict__ ap, const float* __restrict__ bp,
                  const float* __restrict__ cp, const float* __restrict__ dp,
                  float* __restrict__ out) {
    __shared__ int      qidx[L];
    __shared__ int      pidx[BAGS * L];
    __shared__ unsigned bitmap[BAGS * 256];
    __shared__ float    counts_inv[BAGS];
    __shared__ float    q_inv;
    __shared__ __align__(16) float x[BAGS * XS];     // poi embeddings
    __shared__ __align__(16) float qx[H1];           // query embedding
    __shared__ __align__(16) float4 part4[4 * 128];  // query gather partials
    __shared__ float    mp[2 * BAGS * H2];           // poi MLP1 partials
    __shared__ float    qpart[4 * H2];               // query MLP1 partials
    __shared__ float    h1s[BAGS * HS];
    __shared__ float    phs[BAGS * HS];
    __shared__ float    qh1[H2];
    __shared__ float    qh[H2];
    __shared__ float    qsw[L];
    __shared__ float    wpart[16];
    __shared__ int      s_is_last;

    const int tid = threadIdx.x;
    const int bid = blockIdx.x;

    if (bid < NQBLK) {
        // ================= QUERY BLOCK: one b =================
        const int b = bid;
        const float a0 = *qa0p, a1 = *qa1p, a2 = *qa2p;

        if (tid < L) qidx[tid] = qbf[(size_t)b * L + tid];
        __syncthreads();

        if (tid == 0) {
            int c = 0;
#pragma unroll 8
            for (int l = 0; l < L; l++) c += (qidx[l] != PAD);
            q_inv = (c > 0) ? 1.f / (float)c : 0.f;
        }
        __syncthreads();

        // gather: 4 row-chunks in parallel, each 128 float4 slots
        {
            const int g = tid >> 7, slot = tid & 127;
            const float4* cw4 = (const float4*)cw;
            float4 acc = make_float4(0.f, 0.f, 0.f, 0.f);
#pragma unroll 4
            for (int l = g * 32; l < g * 32 + 32; l++) {
                int v = qidx[l];
                if (v != PAD) {
                    float4 r = __ldg(cw4 + (size_t)v * 128 + slot);
                    acc.x += r.x; acc.y += r.y; acc.z += r.z; acc.w += r.w;
                }
            }
            part4[g * 128 + slot] = acc;
        }
        __syncthreads();
        if (tid < 128) {
            float4 s = part4[tid];
            float4 t1 = part4[128 + tid], t2 = part4[256 + tid], t3 = part4[384 + tid];
            s.x += t1.x + t2.x + t3.x;  s.y += t1.y + t2.y + t3.y;
            s.z += t1.z + t2.z + t3.z;  s.w += t1.w + t2.w + t3.w;
            float inv = q_inv;
            float4 o;
            o.x = prelu(s.x * inv, a0); o.y = prelu(s.y * inv, a0);
            o.z = prelu(s.z * inv, a0); o.w = prelu(s.w * inv, a0);
            *(float4*)(qx + tid * 4) = o;
        }
        __syncthreads();

        // MLP1: 256 threads, 4-way d split
        if (tid < 256) {
            int j = tid & 63, p = tid >> 6;
            float acc = 0.f;
            int d0 = p * 128;
#pragma unroll 8
            for (int d = 0; d < 128; d++)
                acc = fmaf(qx[d0 + d], __ldg(qW1 + (d0 + d) * H2 + j), acc);
            qpart[tid] = acc;
        }
        __syncthreads();
        if (tid < H2) {
            float acc = qb1[tid] + qpart[tid] + qpart[64 + tid] +
                        qpart[128 + tid] + qpart[192 + tid];
            qh1[tid] = prelu(acc, a1);
        }
        __syncthreads();
        if (tid < H2) {
            float acc = qb2[tid];
#pragma unroll 8
            for (int d = 0; d < H2; d++)
                acc = fmaf(qh1[d], __ldg(qW2 + d * H2 + tid), acc);
            __stcg(&g_qh[b * H2 + tid], prelu(acc, a2));
        }
        __syncthreads();
        if (tid == 0) {
            __threadfence();
            atomicExch(&g_qflag[b], 1);
        }
    } else {
        // ================= POI BLOCK: 4 (b,k) pairs, same b =================
        const int pair0 = (bid - NQBLK) * BAGS;
        const int bb = pair0 >> 5;
        const float a0 = *pa0p, a1 = *pa1p, a2 = *pa2p;
        const float ind_a = *indap;

        for (int t = tid; t < BAGS * L; t += NT)
            pidx[t] = pbf[(size_t)pair0 * L + t];
        if (tid < L) qidx[tid] = qbf[(size_t)bb * L + tid];
        for (int t = tid; t < BAGS * 256; t += NT)
            bitmap[t] = 0u;
        __syncthreads();

        if (tid < BAGS) {
            const int* ip = &pidx[tid * L];
            int c = 0;
#pragma unroll 8
            for (int l = 0; l < L; l++) c += (ip[l] != PAD);
            counts_inv[tid] = (c > 0) ? 1.f / (float)c : 0.f;
        }
        for (int t = tid; t < BAGS * L; t += NT) {
            int v = pidx[t];
            if (v != PAD)
                atomicOr(&bitmap[(t >> 7) * 256 + (v >> 5)], 1u << (v & 31));
        }
        __syncthreads();

        // ---- 4 poi bags gathered in one parallel phase ----
        {
            const int g = tid >> 7, slot = tid & 127;
            const int* ip = &pidx[g * L];
            const float4* cw4 = (const float4*)cw;
            float4 acc = make_float4(0.f, 0.f, 0.f, 0.f);
#pragma unroll 4
            for (int l = 0; l < L; l++) {
                int v = ip[l];
                if (v != PAD) {
                    float4 r = __ldg(cw4 + (size_t)v * 128 + slot);
                    acc.x += r.x; acc.y += r.y; acc.z += r.z; acc.w += r.w;
                }
            }
            float inv = counts_inv[g];
            float4 o;
            o.x = prelu(acc.x * inv, a0); o.y = prelu(acc.y * inv, a0);
            o.z = prelu(acc.z * inv, a0); o.w = prelu(acc.w * inv, a0);
            *(float4*)(&x[g * XS] + slot * 4) = o;
        }
        __syncthreads();

        // ---- MLP1: 512 threads, 2-way d split ----
        {
            int j = tid & 63, g = (tid >> 6) & 3, half = tid >> 8;
            const float* xg = &x[g * XS + half * 256];
            const float* w = pW1 + (size_t)(half * 256) * H2 + j;
            float acc = 0.f;
#pragma unroll 8
            for (int d = 0; d < 256; d++)
                acc = fmaf(xg[d], __ldg(w + d * H2), acc);
            mp[half * 256 + g * 64 + j] = acc;
        }
        __syncthreads();
        if (tid < 256) {
            int j = tid & 63, g = tid >> 6;
            h1s[g * HS + j] = prelu(pb1[j] + mp[g * 64 + j] + mp[256 + g * 64 + j], a1);
        }
        __syncthreads();
        // ---- MLP2 ----
        if (tid < 256) {
            int j = tid & 63, g = tid >> 6;
            const float* hg = &h1s[g * HS];
            float acc = pb2[j];
#pragma unroll 8
            for (int d = 0; d < H2; d++)
                acc = fmaf(hg[d], __ldg(pW2 + d * H2 + j), acc);
            phs[g * HS + j] = prelu(acc, a2);
        }

        // ---- wait for this b's query_hidden ----
        if (tid == 0) {
            while (((volatile int*)g_qflag)[bb] == 0) {}
            __threadfence();
        }
        __syncthreads();
        if (tid < H2) qh[tid] = __ldcg(&g_qh[bb * H2 + tid]);
        __syncthreads();

        // ---- q-side switch per query index i ----
        if (tid < L) {
            int v = qidx[tid];
            float s = 0.f;
            if (v != PAD) {
                const float* qr = qew + (size_t)v * H2;
                float qd = 0.f;
#pragma unroll 8
                for (int h = 0; h < H2; h++) qd = fmaf(qh[h], __ldg(qr + h), qd);
                s = prelu(qd, ind_a) + 1.f;
            }
            qsw[tid] = s;
        }
        __syncthreads();

        // ---- probe + p-side dot; warp-shuffle reduction ----
        {
            int g = tid >> 7, i = tid & 127;
            int v = qidx[i];
            float val = 0.f;
            if (v != PAD && (bitmap[g * 256 + (v >> 5)] >> (v & 31)) & 1u) {
                const float* pr = pew + (size_t)v * H2;
                const float* ph = &phs[g * HS];
                float pd = 0.f;
#pragma unroll 8
                for (int h = 0; h < H2; h++) pd = fmaf(ph[h], __ldg(pr + h), pd);
                val = qsw[i] * (prelu(pd, ind_a) + 1.f);
            }
#pragma unroll
            for (int off = 16; off > 0; off >>= 1)
                val += __shfl_xor_sync(0xffffffffu, val, off);
            if ((tid & 31) == 0) wpart[tid >> 5] = val;
        }
        __syncthreads();
        if (tid < BAGS) {
            float s = wpart[tid * 4] + wpart[tid * 4 + 1] +
                      wpart[tid * 4 + 2] + wpart[tid * 4 + 3];
            __stcg(&g_ts[pair0 + tid], s);
        }
        __syncthreads();
    }

    // ================= arrival + last-block epilogue =================
    if (tid == 0) {
        __threadfence();
        s_is_last = (atomicAdd(&g_counter, 1) == NBLK - 1);
    }
    __syncthreads();
    if (s_is_last) {
        float* tsbuf = x;             // reuse smem (>= 1024 floats)
        float* mx = qsw;              // reuse smem (32 floats)
#pragma unroll
        for (int it = 0; it < 2; it++) {
            int t = tid + it * NT;
            tsbuf[t] = __ldcg(&g_ts[t]);
        }
        __syncthreads();
        if (tid < B) {
            float m = tsbuf[tid * K];
#pragma unroll 8
            for (int k = 1; k < K; k++) m = fmaxf(m, tsbuf[tid * K + k]);
            mx[tid] = m;
        }
        __syncthreads();
        const float A = *ap, Bc = *bp, C = *cp, D = *dp;
#pragma unroll
        for (int it = 0; it < 2; it++) {
            int t = tid + it * NT;
            int b = t >> 5, k = t & 31;
            float ts = tsbuf[t];
            float m = mx[b];
            float tsn = (2.f * ts - m) / (m + 1e-6f);
            float dx = qloc[b * 2]     - ploc[t * 2];
            float dy = qloc[b * 2 + 1] - ploc[t * 2 + 1];
            float dist_sim = -logf(sqrtf(dx * dx + dy * dy) + 1.f);
            float sig = 1.f / (1.f + expf(-(A * tsn + Bc)));
            out[t] = (C - sig) * (dist_sim - D);
        }
        // reset flags/counter for the next graph replay
        if (tid < B) g_qflag[tid] = 0;
        if (tid == 0) { __threadfence(); g_counter = 0; }
    }
}

// ---------------------------------------------------------------------------
extern "C" void kernel_launch(void* const* d_in, const int* in_sizes, int n_in,
                              void* d_out, int out_size) {
    const int*   qbf  = (const int*)d_in[0];
    const int*   pbf  = (const int*)d_in[1];
    const float* qloc = (const float*)d_in[2];
    const float* ploc = (const float*)d_in[3];
    const float* cw   = (const float*)d_in[4];
    const float* qW1  = (const float*)d_in[5];
    const float* qb1  = (const float*)d_in[6];
    const float* qW2  = (const float*)d_in[7];
    const float* qb2  = (const float*)d_in[8];
    const float* pW1  = (const float*)d_in[9];
    const float* pb1  = (const float*)d_in[10];
    const float* pW2  = (const float*)d_in[11];
    const float* pb2  = (const float*)d_in[12];
    const float* qew  = (const float*)d_in[13];
    const float* pew  = (const float*)d_in[14];
    const float* qa0  = (const float*)d_in[15];
    const float* qa1  = (const float*)d_in[16];
    const float* qa2  = (const float*)d_in[17];
    const float* pa0  = (const float*)d_in[18];
    const float* pa1  = (const float*)d_in[19];
    const float* pa2  = (const float*)d_in[20];
    const float* inda = (const float*)d_in[21];
    const float* a    = (const float*)d_in[22];
    const float* b    = (const float*)d_in[23];
    const float* c    = (const float*)d_in[24];
    const float* d    = (const float*)d_in[25];
    float* out = (float*)d_out;

    urban_kernel<<<NBLK, NT>>>(qbf, pbf, qloc, ploc, cw,
                               qW1, qb1, qW2, qb2,
                               pW1, pb1, pW2, pb2,
                               qew, pew,
                               qa0, qa1, qa2, pa0, pa1, pa2,
                               inda, a, b, c, d, out);
}

// round 6
// speedup vs baseline: 2.4221x; 1.3067x over previous
#include <cuda_runtime.h>
#include <cuda_bf16.h>
#include <math.h>

#define PAD 8192
#define B 32
#define K 32
#define L 128
#define H1 512
#define H2 64
#define BAGS 4
#define NT 512
#define XS 516          // float stride per poi bag (2064 B, 16B multiple)
#define HS 68           // multiple of 4 -> float4-safe sub-arrays
#define NQBLK 32
#define NPBLK 256
#define NBLK (NQBLK + NPBLK)

__device__ float g_qh[B * H2];
__device__ float g_ts[B * K];
__device__ int   g_qflag[B];
__device__ int   g_counter;

__device__ __forceinline__ float prelu(float x, float a) {
    return x >= 0.f ? x : a * x;
}

__global__ __launch_bounds__(NT, 2)
void urban_kernel(const int* __restrict__ qbf,
                  const int* __restrict__ pbf,
                  const float* __restrict__ qloc,
                  const float* __restrict__ ploc,
                  const float* __restrict__ cw,
                  const float* __restrict__ qW1, const float* __restrict__ qb1,
                  const float* __restrict__ qW2, const float* __restrict__ qb2,
                  const float* __restrict__ pW1, const float* __restrict__ pb1,
                  const float* __restrict__ pW2, const float* __restrict__ pb2,
                  const float* __restrict__ qew, const float* __restrict__ pew,
                  const float* __restrict__ qa0p, const float* __restrict__ qa1p,
                  const float* __restrict__ qa2p, const float* __restrict__ pa0p,
                  const float* __restrict__ pa1p, const float* __restrict__ pa2p,
                  const float* __restrict__ indap,
                  const float* __restrict__ ap, const float* __restrict__ bp,
                  const float* __restrict__ cp, const float* __restrict__ dp,
                  float* __restrict__ out) {
    __shared__ int      qidx[L];
    __shared__ int      pidx[BAGS * L];
    __shared__ unsigned bitmap[BAGS * 256];
    __shared__ float    counts_inv[BAGS];
    __shared__ float    q_inv;
    __shared__ __align__(16) float x[BAGS * XS];
    __shared__ __align__(16) float qx[H1];
    __shared__ __align__(16) float4 part4[4 * 128];
    __shared__ float    mp[8 * 256];          // multi-bag MLP partials
    __shared__ float    qpart[8 * 64];
    __shared__ __align__(16) float h1s[BAGS * HS];
    __shared__ __align__(16) float phs[BAGS * HS];
    __shared__ float    qh1[H2];
    __shared__ __align__(16) float qh[H2];
    __shared__ float    qsw[L];
    __shared__ float    wpart[16];
    __shared__ int      s_is_last;

    const int tid = threadIdx.x;
    const int bid = blockIdx.x;

    if (bid < NQBLK) {
        // ================= QUERY BLOCK: one b =================
        const int b = bid;
        const float a0 = *qa0p, a1 = *qa1p, a2 = *qa2p;

        if (tid < L) qidx[tid] = qbf[(size_t)b * L + tid];
        __syncthreads();

        if (tid == 0) {
            int c = 0;
#pragma unroll 8
            for (int l = 0; l < L; l++) c += (qidx[l] != PAD);
            q_inv = (c > 0) ? 1.f / (float)c : 0.f;
        }
        __syncthreads();

        // gather: 4 row-chunks in parallel (unconditional masked loads)
        {
            const int g = tid >> 7, slot = tid & 127;
            const float4* cw4 = (const float4*)cw;
            float4 acc = make_float4(0.f, 0.f, 0.f, 0.f);
#pragma unroll 4
            for (int l = g * 32; l < g * 32 + 32; l++) {
                int v = qidx[l];
                float m = (v != PAD) ? 1.f : 0.f;
                float4 r = __ldg(cw4 + (size_t)v * 128 + slot);
                acc.x = fmaf(m, r.x, acc.x); acc.y = fmaf(m, r.y, acc.y);
                acc.z = fmaf(m, r.z, acc.z); acc.w = fmaf(m, r.w, acc.w);
            }
            part4[g * 128 + slot] = acc;
        }
        __syncthreads();
        if (tid < 128) {
            float4 s = part4[tid];
            float4 t1 = part4[128 + tid], t2 = part4[256 + tid], t3 = part4[384 + tid];
            s.x += t1.x + t2.x + t3.x;  s.y += t1.y + t2.y + t3.y;
            s.z += t1.z + t2.z + t3.z;  s.w += t1.w + t2.w + t3.w;
            float inv = q_inv;
            float4 o;
            o.x = prelu(s.x * inv, a0); o.y = prelu(s.y * inv, a0);
            o.z = prelu(s.z * inv, a0); o.w = prelu(s.w * inv, a0);
            *(float4*)(qx + tid * 4) = o;
        }
        __syncthreads();

        // MLP1: thread = (j, dp), 8 d-parts of 64
        {
            int j = tid & 63, dpp = tid >> 6;
            const float* w = qW1 + (size_t)(dpp * 64) * H2 + j;
            const float* xq = &qx[dpp * 64];
            float acc = 0.f;
#pragma unroll 8
            for (int d = 0; d < 64; d++)
                acc = fmaf(xq[d], __ldg(w + d * H2), acc);
            qpart[dpp * 64 + j] = acc;
        }
        __syncthreads();
        if (tid < H2) {
            float acc = qb1[tid];
#pragma unroll
            for (int p = 0; p < 8; p++) acc += qpart[p * 64 + tid];
            qh1[tid] = prelu(acc, a1);
        }
        __syncthreads();
        // MLP2: thread = (j, dp), 4 parts of 16
        if (tid < 256) {
            int j = tid & 63, dpp = tid >> 6;
            const float* w = qW2 + (size_t)(dpp * 16) * H2 + j;
            float acc = 0.f;
#pragma unroll
            for (int d = 0; d < 16; d++)
                acc = fmaf(qh1[dpp * 16 + d], __ldg(w + d * H2), acc);
            qpart[dpp * 64 + j] = acc;
        }
        __syncthreads();
        if (tid < H2) {
            float acc = qb2[tid] + qpart[tid] + qpart[64 + tid] +
                        qpart[128 + tid] + qpart[192 + tid];
            __stcg(&g_qh[b * H2 + tid], prelu(acc, a2));
        }
        __syncthreads();
        if (tid == 0) {
            __threadfence();
            atomicExch(&g_qflag[b], 1);
        }
    } else {
        // ================= POI BLOCK: 4 (b,k) pairs, same b =================
        const int pair0 = (bid - NQBLK) * BAGS;
        const int bb = pair0 >> 5;
        const float a0 = *pa0p, a1 = *pa1p, a2 = *pa2p;
        const float ind_a = *indap;

        for (int t = tid; t < BAGS * L; t += NT)
            pidx[t] = pbf[(size_t)pair0 * L + t];
        if (tid < L) qidx[tid] = qbf[(size_t)bb * L + tid];
        for (int t = tid; t < BAGS * 256; t += NT)
            bitmap[t] = 0u;
        __syncthreads();

        if (tid < BAGS) {
            const int* ip = &pidx[tid * L];
            int c = 0;
#pragma unroll 8
            for (int l = 0; l < L; l++) c += (ip[l] != PAD);
            counts_inv[tid] = (c > 0) ? 1.f / (float)c : 0.f;
        }
        for (int t = tid; t < BAGS * L; t += NT) {
            int v = pidx[t];
            if (v != PAD)
                atomicOr(&bitmap[(t >> 7) * 256 + (v >> 5)], 1u << (v & 31));
        }
        __syncthreads();

        // ---- 4 poi bags gathered in one phase (unconditional masked loads) ----
        {
            const int g = tid >> 7, slot = tid & 127;
            const int* ip = &pidx[g * L];
            const float4* cw4 = (const float4*)cw;
            float4 acc = make_float4(0.f, 0.f, 0.f, 0.f);
#pragma unroll 4
            for (int l = 0; l < L; l++) {
                int v = ip[l];
                float m = (v != PAD) ? 1.f : 0.f;
                float4 r = __ldg(cw4 + (size_t)v * 128 + slot);
                acc.x = fmaf(m, r.x, acc.x); acc.y = fmaf(m, r.y, acc.y);
                acc.z = fmaf(m, r.z, acc.z); acc.w = fmaf(m, r.w, acc.w);
            }
            float inv = counts_inv[g];
            float4 o;
            o.x = prelu(acc.x * inv, a0); o.y = prelu(acc.y * inv, a0);
            o.z = prelu(acc.z * inv, a0); o.w = prelu(acc.w * inv, a0);
            *(float4*)(&x[g * XS] + slot * 4) = o;
        }
        __syncthreads();

        // ---- MLP1: thread = (j, dp); ONE W1 load feeds 4 bag-accumulators ----
        {
            int j = tid & 63, dpp = tid >> 6;   // 8 d-parts of 64
            const float* w = pW1 + (size_t)(dpp * 64) * H2 + j;
            const float* x0 = &x[0 * XS + dpp * 64];
            const float* x1 = &x[1 * XS + dpp * 64];
            const float* x2 = &x[2 * XS + dpp * 64];
            const float* x3 = &x[3 * XS + dpp * 64];
            float f0 = 0.f, f1 = 0.f, f2 = 0.f, f3 = 0.f;
#pragma unroll 8
            for (int d = 0; d < 64; d++) {
                float wv = __ldg(w + d * H2);
                f0 = fmaf(x0[d], wv, f0);
                f1 = fmaf(x1[d], wv, f1);
                f2 = fmaf(x2[d], wv, f2);
                f3 = fmaf(x3[d], wv, f3);
            }
            mp[dpp * 256 + j]       = f0;
            mp[dpp * 256 + 64 + j]  = f1;
            mp[dpp * 256 + 128 + j] = f2;
            mp[dpp * 256 + 192 + j] = f3;
        }
        __syncthreads();
        if (tid < 256) {
            int j = tid & 63, g = tid >> 6;
            float acc = pb1[j];
#pragma unroll
            for (int p = 0; p < 8; p++) acc += mp[p * 256 + g * 64 + j];
            h1s[g * HS + j] = prelu(acc, a1);
        }
        __syncthreads();
        // ---- MLP2: thread = (j, dp of 16); one W2 load feeds 4 bags ----
        if (tid < 256) {
            int j = tid & 63, dpp = tid >> 6;
            const float* w = pW2 + (size_t)(dpp * 16) * H2 + j;
            float f0 = 0.f, f1 = 0.f, f2 = 0.f, f3 = 0.f;
#pragma unroll
            for (int d = 0; d < 16; d++) {
                float wv = __ldg(w + d * H2);
                int dd = dpp * 16 + d;
                f0 = fmaf(h1s[0 * HS + dd], wv, f0);
                f1 = fmaf(h1s[1 * HS + dd], wv, f1);
                f2 = fmaf(h1s[2 * HS + dd], wv, f2);
                f3 = fmaf(h1s[3 * HS + dd], wv, f3);
            }
            mp[dpp * 256 + j]       = f0;
            mp[dpp * 256 + 64 + j]  = f1;
            mp[dpp * 256 + 128 + j] = f2;
            mp[dpp * 256 + 192 + j] = f3;
        }
        __syncthreads();
        if (tid < 256) {
            int j = tid & 63, g = tid >> 6;
            float acc = pb2[j] + mp[g * 64 + j] + mp[256 + g * 64 + j] +
                        mp[512 + g * 64 + j] + mp[768 + g * 64 + j];
            phs[g * HS + j] = prelu(acc, a2);
        }

        // ---- wait for this b's query_hidden ----
        if (tid == 0) {
            while (((volatile int*)g_qflag)[bb] == 0) {}
            __threadfence();
        }
        __syncthreads();
        if (tid < H2) qh[tid] = __ldcg(&g_qh[bb * H2 + tid]);
        __syncthreads();

        // ---- q-side switch per query index i (vectorized dot) ----
        if (tid < L) {
            int v = qidx[tid];
            float s = 0.f;
            if (v != PAD) {
                const float4* qr4 = (const float4*)(qew + (size_t)v * H2);
                const float4* qh4 = (const float4*)qh;
                float qd = 0.f;
#pragma unroll
                for (int h = 0; h < 16; h++) {
                    float4 r = __ldg(qr4 + h), q = qh4[h];
                    qd += r.x * q.x + r.y * q.y + r.z * q.z + r.w * q.w;
                }
                s = prelu(qd, ind_a) + 1.f;
            }
            qsw[tid] = s;
        }
        __syncthreads();

        // ---- probe + p-side dot; warp-shuffle reduction ----
        {
            int g = tid >> 7, i = tid & 127;
            int v = qidx[i];
            float val = 0.f;
            if (v != PAD && (bitmap[g * 256 + (v >> 5)] >> (v & 31)) & 1u) {
                const float4* pr4 = (const float4*)(pew + (size_t)v * H2);
                const float4* ph4 = (const float4*)(&phs[g * HS]);
                float pd = 0.f;
#pragma unroll
                for (int h = 0; h < 16; h++) {
                    float4 r = __ldg(pr4 + h), p = ph4[h];
                    pd += r.x * p.x + r.y * p.y + r.z * p.z + r.w * p.w;
                }
                val = qsw[i] * (prelu(pd, ind_a) + 1.f);
            }
#pragma unroll
            for (int off = 16; off > 0; off >>= 1)
                val += __shfl_xor_sync(0xffffffffu, val, off);
            if ((tid & 31) == 0) wpart[tid >> 5] = val;
        }
        __syncthreads();
        if (tid < BAGS) {
            float s = wpart[tid * 4] + wpart[tid * 4 + 1] +
                      wpart[tid * 4 + 2] + wpart[tid * 4 + 3];
            __stcg(&g_ts[pair0 + tid], s);
        }
        __syncthreads();
    }

    // ================= arrival + last-block epilogue =================
    if (tid == 0) {
        __threadfence();
        s_is_last = (atomicAdd(&g_counter, 1) == NBLK - 1);
    }
    __syncthreads();
    if (s_is_last) {
        float* tsbuf = x;
        float* mx = qsw;
#pragma unroll
        for (int it = 0; it < 2; it++) {
            int t = tid + it * NT;
            tsbuf[t] = __ldcg(&g_ts[t]);
        }
        __syncthreads();
        if (tid < B) {
            float m = tsbuf[tid * K];
#pragma unroll 8
            for (int k = 1; k < K; k++) m = fmaxf(m, tsbuf[tid * K + k]);
            mx[tid] = m;
        }
        __syncthreads();
        const float A = *ap, Bc = *bp, C = *cp, D = *dp;
#pragma unroll
        for (int it = 0; it < 2; it++) {
            int t = tid + it * NT;
            int b = t >> 5;
            float ts = tsbuf[t];
            float m = mx[b];
            float tsn = (2.f * ts - m) / (m + 1e-6f);
            float dx = qloc[b * 2]     - ploc[t * 2];
            float dy = qloc[b * 2 + 1] - ploc[t * 2 + 1];
            float dist_sim = -logf(sqrtf(dx * dx + dy * dy) + 1.f);
            float sig = 1.f / (1.f + expf(-(A * tsn + Bc)));
            out[t] = (C - sig) * (dist_sim - D);
        }
        if (tid < B) g_qflag[tid] = 0;
        if (tid == 0) { __threadfence(); g_counter = 0; }
    }
}

// ---------------------------------------------------------------------------
extern "C" void kernel_launch(void* const* d_in, const int* in_sizes, int n_in,
                              void* d_out, int out_size) {
    const int*   qbf  = (const int*)d_in[0];
    const int*   pbf  = (const int*)d_in[1];
    const float* qloc = (const float*)d_in[2];
    const float* ploc = (const float*)d_in[3];
    const float* cw   = (const float*)d_in[4];
    const float* qW1  = (const float*)d_in[5];
    const float* qb1  = (const float*)d_in[6];
    const float* qW2  = (const float*)d_in[7];
    const float* qb2  = (const float*)d_in[8];
    const float* pW1  = (const float*)d_in[9];
    const float* pb1  = (const float*)d_in[10];
    const float* pW2  = (const float*)d_in[11];
    const float* pb2  = (const float*)d_in[12];
    const float* qew  = (const float*)d_in[13];
    const float* pew  = (const float*)d_in[14];
    const float* qa0  = (const float*)d_in[15];
    const float* qa1  = (const float*)d_in[16];
    const float* qa2  = (const float*)d_in[17];
    const float* pa0  = (const float*)d_in[18];
    const float* pa1  = (const float*)d_in[19];
    const float* pa2  = (const float*)d_in[20];
    const float* inda = (const float*)d_in[21];
    const float* a    = (const float*)d_in[22];
    const float* b    = (const float*)d_in[23];
    const float* c    = (const float*)d_in[24];
    const float* d    = (const float*)d_in[25];
    float* out = (float*)d_out;

    urban_kernel<<<NBLK, NT>>>(qbf, pbf, qloc, ploc, cw,
                               qW1, qb1, qW2, qb2,
                               pW1, pb1, pW2, pb2,
                               qew, pew,
                               qa0, qa1, qa2, pa0, pa1, pa2,
                               inda, a, b, c, d, out);
}

// round 7
// speedup vs baseline: 2.7651x; 1.1416x over previous
#include <cuda_runtime.h>
#include <cuda_bf16.h>
#include <math.h>

#define PAD 8192
#define B 32
#define K 32
#define L 128
#define H1 512
#define H2 64
#define BAGS 4
#define NT 512
#define XS 516          // float stride per poi bag (16B multiple)
#define HS 68
#define NQBLK 32
#define NPBLK 256
#define NBLK (NQBLK + NPBLK)

__device__ float g_qsw[B * L];    // per-b q-side switch values
__device__ float g_ts[B * K];
__device__ int   g_qflag[B];
__device__ int   g_counter;

__device__ __forceinline__ float prelu(float x, float a) {
    return x >= 0.f ? x : a * x;
}

__global__ __launch_bounds__(NT, 2)
void urban_kernel(const int* __restrict__ qbf,
                  const int* __restrict__ pbf,
                  const float* __restrict__ qloc,
                  const float* __restrict__ ploc,
                  const float* __restrict__ cw,
                  const float* __restrict__ qW1, const float* __restrict__ qb1,
                  const float* __restrict__ qW2, const float* __restrict__ qb2,
                  const float* __restrict__ pW1, const float* __restrict__ pb1,
                  const float* __restrict__ pW2, const float* __restrict__ pb2,
                  const float* __restrict__ qew, const float* __restrict__ pew,
                  const float* __restrict__ qa0p, const float* __restrict__ qa1p,
                  const float* __restrict__ qa2p, const float* __restrict__ pa0p,
                  const float* __restrict__ pa1p, const float* __restrict__ pa2p,
                  const float* __restrict__ indap,
                  const float* __restrict__ ap, const float* __restrict__ bp,
                  const float* __restrict__ cp, const float* __restrict__ dp,
                  float* __restrict__ out) {
    __shared__ int      qidx[L];
    __shared__ int      pidx[BAGS * L];
    __shared__ unsigned bitmap[BAGS * 256];
    __shared__ __align__(16) float x[BAGS * XS];     // also epilogue scratch
    __shared__ __align__(16) float qx[H1];
    __shared__ float    mp[8 * 256];
    __shared__ float    qpart[8 * 64];
    __shared__ __align__(16) float h1s[BAGS * HS];
    __shared__ __align__(16) float phs[BAGS * HS];
    __shared__ float    qh1[H2];
    __shared__ __align__(16) float qh[H2];
    __shared__ float    qsw[L];                       // also epilogue scratch
    __shared__ float    wpart[16];
    __shared__ int      s_is_last;

    const int tid = threadIdx.x;
    const int bid = blockIdx.x;

    if (bid < NQBLK) {
        // ================= QUERY BLOCK: one b =================
        const int b = bid;
        const float a0 = *qa0p, a1 = *qa1p, a2 = *qa2p;
        const float ind_a = *indap;

        if (tid < L) qidx[tid] = qbf[(size_t)b * L + tid];
        __syncthreads();

        // gather: one column per thread, count fused
        {
            const int c = tid;
            float acc = 0.f;
            int cnt = 0;
#pragma unroll 4
            for (int l = 0; l < L; l++) {
                int v = qidx[l];
                bool ok = (v != PAD);
                cnt += ok;
                acc = fmaf(ok ? 1.f : 0.f, __ldg(cw + (size_t)v * H1 + c), acc);
            }
            float inv = cnt > 0 ? 1.f / (float)cnt : 0.f;
            qx[c] = prelu(acc * inv, a0);
        }
        __syncthreads();

        // MLP1: thread = (j, dp), 8 d-parts of 64
        {
            int j = tid & 63, dpp = tid >> 6;
            const float* w = qW1 + (size_t)(dpp * 64) * H2 + j;
            const float* xq = &qx[dpp * 64];
            float acc = 0.f;
#pragma unroll 8
            for (int d = 0; d < 64; d++)
                acc = fmaf(xq[d], __ldg(w + d * H2), acc);
            qpart[dpp * 64 + j] = acc;
        }
        __syncthreads();
        if (tid < H2) {
            float acc = qb1[tid];
#pragma unroll
            for (int p = 0; p < 8; p++) acc += qpart[p * 64 + tid];
            qh1[tid] = prelu(acc, a1);
        }
        __syncthreads();
        if (tid < 256) {
            int j = tid & 63, dpp = tid >> 6;
            const float* w = qW2 + (size_t)(dpp * 16) * H2 + j;
            float acc = 0.f;
#pragma unroll
            for (int d = 0; d < 16; d++)
                acc = fmaf(qh1[dpp * 16 + d], __ldg(w + d * H2), acc);
            qpart[dpp * 64 + j] = acc;
        }
        __syncthreads();
        if (tid < H2) {
            float acc = qb2[tid] + qpart[tid] + qpart[64 + tid] +
                        qpart[128 + tid] + qpart[192 + tid];
            qh[tid] = prelu(acc, a2);
        }
        __syncthreads();

        // q-side switch for all 128 query indices, published globally
        if (tid < L) {
            int v = qidx[tid];
            float s = 0.f;
            if (v != PAD) {
                const float4* qr4 = (const float4*)(qew + (size_t)v * H2);
                const float4* qh4 = (const float4*)qh;
                float qd = 0.f;
#pragma unroll
                for (int h = 0; h < 16; h++) {
                    float4 r = __ldg(qr4 + h), q = qh4[h];
                    qd += r.x * q.x + r.y * q.y + r.z * q.z + r.w * q.w;
                }
                s = prelu(qd, ind_a) + 1.f;
            }
            __stcg(&g_qsw[b * L + tid], s);
        }
        __syncthreads();
        if (tid == 0) {
            __threadfence();
            atomicExch(&g_qflag[b], 1);
        }
    } else {
        // ================= POI BLOCK: 4 (b,k) pairs, same b =================
        const int pair0 = (bid - NQBLK) * BAGS;
        const int bb = pair0 >> 5;
        const float a0 = *pa0p, a1 = *pa1p, a2 = *pa2p;
        const float ind_a = *indap;

        for (int t = tid; t < BAGS * L; t += NT)
            pidx[t] = pbf[(size_t)pair0 * L + t];
        if (tid < L) qidx[tid] = qbf[(size_t)bb * L + tid];
        for (int t = tid; t < BAGS * 256; t += NT)
            bitmap[t] = 0u;
        __syncthreads();

        // ---- 4 poi bags gathered in one phase; counts fused ----
        {
            const int g = tid >> 7, slot = tid & 127;
            const int* ip = &pidx[g * L];
            const float4* cw4 = (const float4*)cw;
            float4 acc = make_float4(0.f, 0.f, 0.f, 0.f);
            int cnt = 0;
#pragma unroll 4
            for (int l = 0; l < L; l++) {
                int v = ip[l];
                bool ok = (v != PAD);
                cnt += ok;
                float m = ok ? 1.f : 0.f;
                float4 r = __ldg(cw4 + (size_t)v * 128 + slot);
                acc.x = fmaf(m, r.x, acc.x); acc.y = fmaf(m, r.y, acc.y);
                acc.z = fmaf(m, r.z, acc.z); acc.w = fmaf(m, r.w, acc.w);
            }
            float inv = cnt > 0 ? 1.f / (float)cnt : 0.f;
            float4 o;
            o.x = prelu(acc.x * inv, a0); o.y = prelu(acc.y * inv, a0);
            o.z = prelu(acc.z * inv, a0); o.w = prelu(acc.w * inv, a0);
            *(float4*)(&x[g * XS] + slot * 4) = o;
        }
        __syncthreads();

        // ---- bitmap build (overlapped with MLP1 phase) ----
        {
            int v = pidx[tid];
            if (v != PAD)
                atomicOr(&bitmap[(tid >> 7) * 256 + (v >> 5)], 1u << (v & 31));
        }
        // ---- MLP1: one W1 load feeds 4 bag-accumulators ----
        {
            int j = tid & 63, dpp = tid >> 6;
            const float* w = pW1 + (size_t)(dpp * 64) * H2 + j;
            const float* x0 = &x[0 * XS + dpp * 64];
            const float* x1 = &x[1 * XS + dpp * 64];
            const float* x2 = &x[2 * XS + dpp * 64];
            const float* x3 = &x[3 * XS + dpp * 64];
            float f0 = 0.f, f1 = 0.f, f2 = 0.f, f3 = 0.f;
#pragma unroll 8
            for (int d = 0; d < 64; d++) {
                float wv = __ldg(w + d * H2);
                f0 = fmaf(x0[d], wv, f0);
                f1 = fmaf(x1[d], wv, f1);
                f2 = fmaf(x2[d], wv, f2);
                f3 = fmaf(x3[d], wv, f3);
            }
            mp[dpp * 256 + j]       = f0;
            mp[dpp * 256 + 64 + j]  = f1;
            mp[dpp * 256 + 128 + j] = f2;
            mp[dpp * 256 + 192 + j] = f3;
        }
        __syncthreads();
        if (tid < 256) {
            int j = tid & 63, g = tid >> 6;
            float acc = pb1[j];
#pragma unroll
            for (int p = 0; p < 8; p++) acc += mp[p * 256 + g * 64 + j];
            h1s[g * HS + j] = prelu(acc, a1);
        }
        __syncthreads();
        // ---- MLP2 ----
        if (tid < 256) {
            int j = tid & 63, dpp = tid >> 6;
            const float* w = pW2 + (size_t)(dpp * 16) * H2 + j;
            float f0 = 0.f, f1 = 0.f, f2 = 0.f, f3 = 0.f;
#pragma unroll
            for (int d = 0; d < 16; d++) {
                float wv = __ldg(w + d * H2);
                int dd = dpp * 16 + d;
                f0 = fmaf(h1s[0 * HS + dd], wv, f0);
                f1 = fmaf(h1s[1 * HS + dd], wv, f1);
                f2 = fmaf(h1s[2 * HS + dd], wv, f2);
                f3 = fmaf(h1s[3 * HS + dd], wv, f3);
            }
            mp[dpp * 256 + j]       = f0;
            mp[dpp * 256 + 64 + j]  = f1;
            mp[dpp * 256 + 128 + j] = f2;
            mp[dpp * 256 + 192 + j] = f3;
        }
        __syncthreads();
        if (tid < 256) {
            int j = tid & 63, g = tid >> 6;
            float acc = pb2[j] + mp[g * 64 + j] + mp[256 + g * 64 + j] +
                        mp[512 + g * 64 + j] + mp[768 + g * 64 + j];
            phs[g * HS + j] = prelu(acc, a2);
        }
        if (tid == 0) {
            while (((volatile int*)g_qflag)[bb] == 0) {}
            __threadfence();
        }
        __syncthreads();
        if (tid < L) qsw[tid] = __ldcg(&g_qsw[bb * L + tid]);
        __syncthreads();

        // ---- probe + p-side dot; warp-shuffle reduction ----
        {
            int g = tid >> 7, i = tid & 127;
            int v = qidx[i];
            float val = 0.f;
            if (v != PAD && (bitmap[g * 256 + (v >> 5)] >> (v & 31)) & 1u) {
                const float4* pr4 = (const float4*)(pew + (size_t)v * H2);
                const float4* ph4 = (const float4*)(&phs[g * HS]);
                float pd = 0.f;
#pragma unroll
                for (int h = 0; h < 16; h++) {
                    float4 r = __ldg(pr4 + h), p = ph4[h];
                    pd += r.x * p.x + r.y * p.y + r.z * p.z + r.w * p.w;
                }
                val = qsw[i] * (prelu(pd, ind_a) + 1.f);
            }
#pragma unroll
            for (int off = 16; off > 0; off >>= 1)
                val += __shfl_xor_sync(0xffffffffu, val, off);
            if ((tid & 31) == 0) wpart[tid >> 5] = val;
        }
        __syncthreads();
        if (tid < BAGS) {
            float s = wpart[tid * 4] + wpart[tid * 4 + 1] +
                      wpart[tid * 4 + 2] + wpart[tid * 4 + 3];
            __stcg(&g_ts[pair0 + tid], s);
        }
        __syncthreads();
    }

    // ================= arrival + last-block epilogue =================
    if (tid == 0) {
        __threadfence();
        s_is_last = (atomicAdd(&g_counter, 1) == NBLK - 1);
    }
    __syncthreads();
    if (s_is_last) {
        float* tsbuf = x;
        float* mx = qsw;
#pragma unroll
        for (int it = 0; it < 2; it++) {
            int t = tid + it * NT;
            tsbuf[t] = __ldcg(&g_ts[t]);
        }
        __syncthreads();
        if (tid < B) {
            float m = tsbuf[tid * K];
#pragma unroll 8
            for (int k = 1; k < K; k++) m = fmaxf(m, tsbuf[tid * K + k]);
            mx[tid] = m;
        }
        __syncthreads();
        const float A = *ap, Bc = *bp, C = *cp, D = *dp;
#pragma unroll
        for (int it = 0; it < 2; it++) {
            int t = tid + it * NT;
            int b = t >> 5;
            float ts = tsbuf[t];
            float m = mx[b];
            float tsn = (2.f * ts - m) / (m + 1e-6f);
            float dx = qloc[b * 2]     - ploc[t * 2];
            float dy = qloc[b * 2 + 1] - ploc[t * 2 + 1];
            float dist_sim = -logf(sqrtf(dx * dx + dy * dy) + 1.f);
            float sig = 1.f / (1.f + expf(-(A * tsn + Bc)));
            out[t] = (C - sig) * (dist_sim - D);
        }
        if (tid < B) g_qflag[tid] = 0;
        if (tid == 0) { __threadfence(); g_counter = 0; }
    }
}

// ---------------------------------------------------------------------------
extern "C" void kernel_launch(void* const* d_in, const int* in_sizes, int n_in,
                              void* d_out, int out_size) {
    const int*   qbf  = (const int*)d_in[0];
    const int*   pbf  = (const int*)d_in[1];
    const float* qloc = (const float*)d_in[2];
    const float* ploc = (const float*)d_in[3];
    const float* cw   = (const float*)d_in[4];
    const float* qW1  = (const float*)d_in[5];
    const float* qb1  = (const float*)d_in[6];
    const float* qW2  = (const float*)d_in[7];
    const float* qb2  = (const float*)d_in[8];
    const float* pW1  = (const float*)d_in[9];
    const float* pb1  = (const float*)d_in[10];
    const float* pW2  = (const float*)d_in[11];
    const float* pb2  = (const float*)d_in[12];
    const float* qew  = (const float*)d_in[13];
    const float* pew  = (const float*)d_in[14];
    const float* qa0  = (const float*)d_in[15];
    const float* qa1  = (const float*)d_in[16];
    const float* qa2  = (const float*)d_in[17];
    const float* pa0  = (const float*)d_in[18];
    const float* pa1  = (const float*)d_in[19];
    const float* pa2  = (const float*)d_in[20];
    const float* inda = (const float*)d_in[21];
    const float* a    = (const float*)d_in[22];
    const float* b    = (const float*)d_in[23];
    const float* c    = (const float*)d_in[24];
    const float* d    = (const float*)d_in[25];
    float* out = (float*)d_out;

    urban_kernel<<<NBLK, NT>>>(qbf, pbf, qloc, ploc, cw,
                               qW1, qb1, qW2, qb2,
                               pW1, pb1, pW2, pb2,
                               qew, pew,
                               qa0, qa1, qa2, pa0, pa1, pa2,
                               inda, a, b, c, d, out);
}